// round 12
// baseline (speedup 1.0000x reference)
#include <cuda_runtime.h>
#include <cuda_bf16.h>
#include <math_constants.h>

// R12: resubmission of R11 (infra failure, never ran).
// gemm1 8-rows-per-warp; merged scan; k_bucket at profiled launch idx 3.

#define N_NODES 100000
#define N_EDGES 3200000
#define C_IN    128
#define HID     64
#define COUT    40

// ---------------- scratch (device globals; no allocation allowed) ----------
__device__ __align__(16) float g_dinv[N_NODES];
__device__ __align__(16) int   g_deg [N_NODES];
__device__ __align__(16) int   g_rowstart[N_NODES];
__device__ __align__(16) int   g_cursor  [N_NODES];
__device__ __align__(16) int2  g_edge[N_EDGES];          // {src, norm bits} dst-sorted
__device__ __align__(16) float g_h1  [N_NODES * HID];    // x @ W1
__device__ __align__(16) float g_h2  [N_NODES * COUT];   // layer-1 output
__device__ int g_idx64;

// ---------------- edge-index accessor (dtype-agnostic) ---------------------
__device__ __forceinline__ void load_edge(const void* ei, int e, int E,
                                          int& src, int& dst) {
    if (g_idx64) {
        const long long* p = (const long long*)ei;
        src = (int)__ldg(&p[e]);
        dst = (int)__ldg(&p[E + e]);
    } else {
        const int* p = (const int*)ei;
        src = __ldg(&p[e]);
        dst = __ldg(&p[E + e]);
    }
}

// ---------------- init: dtype detect (thread 0) + zero degree --------------
__global__ void k_init(const int* __restrict__ ei32, int N) {
    int i = blockIdx.x * blockDim.x + threadIdx.x;
    if (i == 0) {
        int all_zero = 1;
        for (int j = 0; j < 64; j++)
            if (ei32[2 * j + 1] != 0) { all_zero = 0; break; }
        g_idx64 = all_zero;
    }
    int stride = gridDim.x * blockDim.x;
    for (int j = i; j < N; j += stride) g_deg[j] = 0;
}

// ---------------- histogram of dst (= in-degree) ---------------------------
__global__ void k_hist(const void* __restrict__ ei, int E) {
    int e = blockIdx.x * blockDim.x + threadIdx.x;
    if (e < E) {
        int dst;
        if (g_idx64) dst = (int)__ldg(&((const long long*)ei)[E + e]);
        else         dst = __ldg(&((const int*)ei)[E + e]);
        atomicAdd(&g_deg[dst], 1);
    }
}

// ---------------- single-block exclusive scan + cursor + dinv --------------
__global__ void k_scan(int N) {
    __shared__ int s[1024];
    int tid = threadIdx.x;
    int chunk = (N + 1023) / 1024;
    int begin = tid * chunk;
    int endi  = min(begin + chunk, N);

    int sum = 0;
    for (int i = begin; i < endi; i++) sum += g_deg[i];
    s[tid] = sum;
    __syncthreads();
#pragma unroll
    for (int off = 1; off < 1024; off <<= 1) {
        int v = (tid >= off) ? s[tid - off] : 0;
        __syncthreads();
        s[tid] += v;
        __syncthreads();
    }
    int run = s[tid] - sum;   // exclusive prefix of this thread's chunk
    for (int i = begin; i < endi; i++) {
        int d = g_deg[i];
        g_rowstart[i] = run;
        g_cursor[i]   = run;
        g_dinv[i] = (d > 0) ? rsqrtf((float)d) : 0.f;
        run += d;
    }
}

// ---------------- bucket edges by dst (sorted (src, norm) list) ------------
__global__ void k_bucket(const void* __restrict__ ei, int E) {
    int e = blockIdx.x * blockDim.x + threadIdx.x;
    if (e < E) {
        int src, dst;
        load_edge(ei, e, E, src, dst);
        float norm = __ldg(&g_dinv[src]) * __ldg(&g_dinv[dst]);
        int pos = atomicAdd(&g_cursor[dst], 1);
        g_edge[pos] = make_int2(src, __float_as_int(norm));
    }
}

// ---------------- GEMM1: h1 = x @ W1 (8 rows per warp, smem W reuse) -------
__global__ void k_gemm1(const float* __restrict__ x, const float* __restrict__ W1, int N) {
    __shared__ float2 Ws[C_IN * 32];   // [k][colpair]
    int tid = threadIdx.x;
    const float2* W2p = (const float2*)W1;
    for (int i = tid; i < C_IN * 32; i += blockDim.x) Ws[i] = W2p[i];
    __syncthreads();

    int warp = (blockIdx.x * blockDim.x + tid) >> 5;
    int lane = tid & 31;
    int r0 = warp * 8;
    if (r0 >= N) return;

    if (r0 + 7 < N) {
        float2 a[8];
#pragma unroll
        for (int r = 0; r < 8; r++) a[r] = make_float2(0.f, 0.f);
#pragma unroll 8
        for (int k4 = 0; k4 < C_IN / 4; k4++) {
            float2 w0 = Ws[(k4 * 4 + 0) * 32 + lane];
            float2 w1 = Ws[(k4 * 4 + 1) * 32 + lane];
            float2 w2 = Ws[(k4 * 4 + 2) * 32 + lane];
            float2 w3 = Ws[(k4 * 4 + 3) * 32 + lane];
#pragma unroll
            for (int r = 0; r < 8; r++) {
                float4 xv = __ldg((const float4*)(x + (size_t)(r0 + r) * C_IN) + k4);
                a[r].x += xv.x * w0.x + xv.y * w1.x + xv.z * w2.x + xv.w * w3.x;
                a[r].y += xv.x * w0.y + xv.y * w1.y + xv.z * w2.y + xv.w * w3.y;
            }
        }
        float2* hp = (float2*)g_h1;
#pragma unroll
        for (int r = 0; r < 8; r++) hp[(r0 + r) * 32 + lane] = a[r];
    } else {
        for (int r = r0; r < N; r++) {
            const float4* xp = (const float4*)(x + (size_t)r * C_IN);
            float2 acc = make_float2(0.f, 0.f);
#pragma unroll
            for (int k4 = 0; k4 < C_IN / 4; k4++) {
                float4 xv = __ldg(&xp[k4]);
                float2 w0 = Ws[(k4 * 4 + 0) * 32 + lane];
                float2 w1 = Ws[(k4 * 4 + 1) * 32 + lane];
                float2 w2 = Ws[(k4 * 4 + 2) * 32 + lane];
                float2 w3 = Ws[(k4 * 4 + 3) * 32 + lane];
                acc.x += xv.x * w0.x + xv.y * w1.x + xv.z * w2.x + xv.w * w3.x;
                acc.y += xv.x * w0.y + xv.y * w1.y + xv.z * w2.y + xv.w * w3.y;
            }
            ((float2*)g_h1)[r * 32 + lane] = acc;
        }
    }
}

// ---------------- layer1 aggregate + bias + relu + GEMM2 (warp per node) ---
__global__ void k_agg1g2(const float* __restrict__ W2, const float* __restrict__ b1, int N) {
    __shared__ float Ws[HID * COUT + 64];   // padded: o1 path reads up to +63
    __shared__ float b1s[HID];
    int tid = threadIdx.x;
    for (int i = tid; i < HID * COUT + 64; i += blockDim.x)
        Ws[i] = (i < HID * COUT) ? W2[i] : 0.f;
    if (tid < HID) b1s[tid] = b1[tid];
    __syncthreads();

    int row  = (blockIdx.x * blockDim.x + tid) >> 5;
    int lane = tid & 31;
    if (row >= N) return;

    int idx = g_rowstart[row];
    int end = idx + g_deg[row];

    float2 acc = make_float2(0.f, 0.f);
    const float2* h1p = (const float2*)g_h1;

    // peel to 16B alignment for int4 pair loads
    if ((idx & 1) && idx < end) {
        int2 e = __ldg((const int2*)&g_edge[idx]);
        float n = __int_as_float(e.y);
        float2 v = h1p[e.x * 32 + lane];
        acc.x += v.x * n; acc.y += v.y * n;
        idx++;
    }
    int npair = (end - idx) >> 1;
    const int4* p4 = (const int4*)(g_edge + idx);

    int nf = npair & ~3;                      // groups of 4 int4 = 8 edges
    for (int j = 0; j < nf; j += 4) {
        int4 ea = __ldg(&p4[j]);
        int4 eb = __ldg(&p4[j + 1]);
        int4 ec = __ldg(&p4[j + 2]);
        int4 ed = __ldg(&p4[j + 3]);
        float2 v0 = h1p[ea.x * 32 + lane];
        float2 v1 = h1p[ea.z * 32 + lane];
        float2 v2 = h1p[eb.x * 32 + lane];
        float2 v3 = h1p[eb.z * 32 + lane];
        float2 v4 = h1p[ec.x * 32 + lane];
        float2 v5 = h1p[ec.z * 32 + lane];
        float2 v6 = h1p[ed.x * 32 + lane];
        float2 v7 = h1p[ed.z * 32 + lane];
        float n0 = __int_as_float(ea.y), n1 = __int_as_float(ea.w);
        float n2 = __int_as_float(eb.y), n3 = __int_as_float(eb.w);
        float n4 = __int_as_float(ec.y), n5 = __int_as_float(ec.w);
        float n6 = __int_as_float(ed.y), n7 = __int_as_float(ed.w);
        acc.x += v0.x * n0 + v1.x * n1 + v2.x * n2 + v3.x * n3
               + v4.x * n4 + v5.x * n5 + v6.x * n6 + v7.x * n7;
        acc.y += v0.y * n0 + v1.y * n1 + v2.y * n2 + v3.y * n3
               + v4.y * n4 + v5.y * n5 + v6.y * n6 + v7.y * n7;
    }
    for (int j = nf; j < npair; j++) {
        int4 ea = __ldg(&p4[j]);
        float2 v0 = h1p[ea.x * 32 + lane];
        float2 v1 = h1p[ea.z * 32 + lane];
        float n0 = __int_as_float(ea.y), n1 = __int_as_float(ea.w);
        acc.x += v0.x * n0 + v1.x * n1;
        acc.y += v0.y * n0 + v1.y * n1;
    }
    if ((end - idx) & 1) {
        int2 e = __ldg((const int2*)&g_edge[end - 1]);
        float n = __int_as_float(e.y);
        float2 v = h1p[e.x * 32 + lane];
        acc.x += v.x * n; acc.y += v.y * n;
    }

    // relu(agg + b1); lane holds cols 2*lane, 2*lane+1
    float c0 = fmaxf(acc.x + b1s[2 * lane],     0.f);
    float c1 = fmaxf(acc.y + b1s[2 * lane + 1], 0.f);

    float o0 = 0.f, o1 = 0.f;
#pragma unroll
    for (int k = 0; k < HID; k++) {
        float xv = __shfl_sync(0xffffffffu, (k & 1) ? c1 : c0, k >> 1);
        o0 += xv * Ws[k * COUT + lane];
        o1 += xv * Ws[k * COUT + lane + 32];
    }
    g_h2[row * COUT + lane] = o0;
    if (lane < COUT - 32) g_h2[row * COUT + 32 + lane] = o1;
}

// ---------------- layer2 aggregate + bias + log_softmax (warp per node) ----
__global__ void k_agg2fin(const float* __restrict__ b2, float* __restrict__ out, int N) {
    int tid = blockIdx.x * blockDim.x + threadIdx.x;
    int row = tid >> 5;
    int lane = tid & 31;
    if (row >= N) return;

    int idx = g_rowstart[row];
    int end = idx + g_deg[row];
    bool has1 = lane < (COUT - 32);
    int col1  = has1 ? (32 + lane) : lane;   // safe dummy for inactive lanes

    float a0 = 0.f, a1 = 0.f;

    if ((idx & 1) && idx < end) {
        int2 e = __ldg((const int2*)&g_edge[idx]);
        float n = __int_as_float(e.y);
        a0 += g_h2[e.x * COUT + lane] * n;
        a1 += g_h2[e.x * COUT + col1] * n;
        idx++;
    }
    int npair = (end - idx) >> 1;
    const int4* p4 = (const int4*)(g_edge + idx);

    int nf = npair & ~3;
    for (int j = 0; j < nf; j += 4) {
        int4 ea = __ldg(&p4[j]);
        int4 eb = __ldg(&p4[j + 1]);
        int4 ec = __ldg(&p4[j + 2]);
        int4 ed = __ldg(&p4[j + 3]);
        float n0 = __int_as_float(ea.y), n1 = __int_as_float(ea.w);
        float n2 = __int_as_float(eb.y), n3 = __int_as_float(eb.w);
        float n4 = __int_as_float(ec.y), n5 = __int_as_float(ec.w);
        float n6 = __int_as_float(ed.y), n7 = __int_as_float(ed.w);
        float p0 = g_h2[ea.x * COUT + lane], q0 = g_h2[ea.x * COUT + col1];
        float p1 = g_h2[ea.z * COUT + lane], q1 = g_h2[ea.z * COUT + col1];
        float p2 = g_h2[eb.x * COUT + lane], q2 = g_h2[eb.x * COUT + col1];
        float p3 = g_h2[eb.z * COUT + lane], q3 = g_h2[eb.z * COUT + col1];
        float p4v = g_h2[ec.x * COUT + lane], q4 = g_h2[ec.x * COUT + col1];
        float p5 = g_h2[ec.z * COUT + lane], q5 = g_h2[ec.z * COUT + col1];
        float p6 = g_h2[ed.x * COUT + lane], q6 = g_h2[ed.x * COUT + col1];
        float p7 = g_h2[ed.z * COUT + lane], q7 = g_h2[ed.z * COUT + col1];
        a0 += p0 * n0 + p1 * n1 + p2 * n2 + p3 * n3
            + p4v * n4 + p5 * n5 + p6 * n6 + p7 * n7;
        a1 += q0 * n0 + q1 * n1 + q2 * n2 + q3 * n3
            + q4 * n4 + q5 * n5 + q6 * n6 + q7 * n7;
    }
    for (int j = nf; j < npair; j++) {
        int4 ea = __ldg(&p4[j]);
        float n0 = __int_as_float(ea.y), n1 = __int_as_float(ea.w);
        a0 += g_h2[ea.x * COUT + lane] * n0 + g_h2[ea.z * COUT + lane] * n1;
        a1 += g_h2[ea.x * COUT + col1] * n0 + g_h2[ea.z * COUT + col1] * n1;
    }
    if ((end - idx) & 1) {
        int2 e = __ldg((const int2*)&g_edge[end - 1]);
        float n = __int_as_float(e.y);
        a0 += g_h2[e.x * COUT + lane] * n;
        a1 += g_h2[e.x * COUT + col1] * n;
    }

    float v0 = a0 + b2[lane];
    float v1 = has1 ? (a1 + b2[32 + lane]) : -CUDART_INF_F;

    float mx = fmaxf(v0, v1);
#pragma unroll
    for (int o = 16; o; o >>= 1) mx = fmaxf(mx, __shfl_xor_sync(0xffffffffu, mx, o));

    float sm = __expf(v0 - mx) + (has1 ? __expf(v1 - mx) : 0.f);
#pragma unroll
    for (int o = 16; o; o >>= 1) sm += __shfl_xor_sync(0xffffffffu, sm, o);

    float lg = mx + logf(sm);
    out[row * COUT + lane] = v0 - lg;
    if (has1) out[row * COUT + 32 + lane] = v1 - lg;
}

// ---------------- launch ----------------------------------------------------
extern "C" void kernel_launch(void* const* d_in, const int* in_sizes, int n_in,
                              void* d_out, int out_size) {
    const float* x  = (const float*)d_in[0];
    const void*  ei = d_in[1];
    const float* W1 = (const float*)d_in[2];
    const float* b1 = (const float*)d_in[3];
    const float* W2 = (const float*)d_in[4];
    const float* b2 = (const float*)d_in[5];
    float* out = (float*)d_out;

    int N = in_sizes[0] / C_IN;     // 100000
    int E = in_sizes[1] / 2;        // 3200000

    int g1warps = (N + 7) / 8;      // 8 rows per warp
    k_init   <<<256, 256>>>((const int*)ei, N);                 // idx 0
    k_hist   <<<(E + 255) / 256, 256>>>(ei, E);                 // idx 1
    k_scan   <<<1, 1024>>>(N);                                  // idx 2
    k_bucket <<<(E + 255) / 256, 256>>>(ei, E);                 // idx 3 (profiled)
    k_gemm1  <<<(g1warps * 32 + 255) / 256, 256>>>(x, W1, N);   // idx 4
    k_agg1g2 <<<(N * 32 + 255) / 256, 256>>>(W2, b1, N);        // idx 5
    k_agg2fin<<<(N * 32 + 255) / 256, 256>>>(b2, out, N);       // idx 6
}

// round 14
// speedup vs baseline: 1.5588x; 1.5588x over previous
#include <cuda_runtime.h>
#include <cuda_bf16.h>
#include <math_constants.h>

// R14: resubmission of R13 (infra failure, never ran).
// 3-kernel scan restored (R12's merged scan caused +215us); 8-row gemm1 @ idx 3.

#define N_NODES 100000
#define N_EDGES 3200000
#define C_IN    128
#define HID     64
#define COUT    40
#define SCAN_BLK 1024

// ---------------- scratch (device globals; no allocation allowed) ----------
__device__ __align__(16) float g_dinv[N_NODES];
__device__ __align__(16) int   g_deg [N_NODES];
__device__ __align__(16) int   g_rowstart[N_NODES];
__device__ __align__(16) int   g_cursor  [N_NODES];
__device__ __align__(16) int   g_bsum[128];
__device__ __align__(16) int2  g_edge[N_EDGES];          // {src, norm bits} dst-sorted
__device__ __align__(16) float g_h1  [N_NODES * HID];    // x @ W1
__device__ __align__(16) float g_h2  [N_NODES * COUT];   // layer-1 output
__device__ int g_idx64;

// ---------------- edge-index accessor (dtype-agnostic) ---------------------
__device__ __forceinline__ void load_edge(const void* ei, int e, int E,
                                          int& src, int& dst) {
    if (g_idx64) {
        const long long* p = (const long long*)ei;
        src = (int)__ldg(&p[e]);
        dst = (int)__ldg(&p[E + e]);
    } else {
        const int* p = (const int*)ei;
        src = __ldg(&p[e]);
        dst = __ldg(&p[E + e]);
    }
}

// ---------------- init: dtype detect (thread 0) + zero degree --------------
__global__ void k_init(const int* __restrict__ ei32, int N) {
    int i = blockIdx.x * blockDim.x + threadIdx.x;
    if (i == 0) {
        int all_zero = 1;
        for (int j = 0; j < 64; j++)
            if (ei32[2 * j + 1] != 0) { all_zero = 0; break; }
        g_idx64 = all_zero;
    }
    int stride = gridDim.x * blockDim.x;
    for (int j = i; j < N; j += stride) g_deg[j] = 0;
}

// ---------------- histogram of dst (= in-degree) ---------------------------
__global__ void k_hist(const void* __restrict__ ei, int E) {
    int e = blockIdx.x * blockDim.x + threadIdx.x;
    if (e < E) {
        int dst;
        if (g_idx64) dst = (int)__ldg(&((const long long*)ei)[E + e]);
        else         dst = __ldg(&((const int*)ei)[E + e]);
        atomicAdd(&g_deg[dst], 1);
    }
}

// ---------------- scan phase A: per-block exclusive scan -------------------
__global__ void k_scanA(int N) {
    __shared__ int s[SCAN_BLK];
    int tid = threadIdx.x;
    int i = blockIdx.x * SCAN_BLK + tid;
    int own = (i < N) ? g_deg[i] : 0;
    s[tid] = own;
    __syncthreads();
#pragma unroll
    for (int off = 1; off < SCAN_BLK; off <<= 1) {
        int v = (tid >= off) ? s[tid - off] : 0;
        __syncthreads();
        s[tid] += v;
        __syncthreads();
    }
    if (i < N) g_rowstart[i] = s[tid] - own;
    if (tid == SCAN_BLK - 1) g_bsum[blockIdx.x] = s[tid];
}

// ---------------- GEMM1: h1 = x @ W1 (8 rows per warp, smem W reuse) -------
__global__ void k_gemm1(const float* __restrict__ x, const float* __restrict__ W1, int N) {
    __shared__ float2 Ws[C_IN * 32];   // [k][colpair]
    int tid = threadIdx.x;
    const float2* W2p = (const float2*)W1;
    for (int i = tid; i < C_IN * 32; i += blockDim.x) Ws[i] = W2p[i];
    __syncthreads();

    int warp = (blockIdx.x * blockDim.x + tid) >> 5;
    int lane = tid & 31;
    int r0 = warp * 8;
    if (r0 >= N) return;

    if (r0 + 7 < N) {
        float2 a[8];
#pragma unroll
        for (int r = 0; r < 8; r++) a[r] = make_float2(0.f, 0.f);
#pragma unroll 8
        for (int k4 = 0; k4 < C_IN / 4; k4++) {
            float2 w0 = Ws[(k4 * 4 + 0) * 32 + lane];
            float2 w1 = Ws[(k4 * 4 + 1) * 32 + lane];
            float2 w2 = Ws[(k4 * 4 + 2) * 32 + lane];
            float2 w3 = Ws[(k4 * 4 + 3) * 32 + lane];
#pragma unroll
            for (int r = 0; r < 8; r++) {
                float4 xv = __ldg((const float4*)(x + (size_t)(r0 + r) * C_IN) + k4);
                a[r].x += xv.x * w0.x + xv.y * w1.x + xv.z * w2.x + xv.w * w3.x;
                a[r].y += xv.x * w0.y + xv.y * w1.y + xv.z * w2.y + xv.w * w3.y;
            }
        }
        float2* hp = (float2*)g_h1;
#pragma unroll
        for (int r = 0; r < 8; r++) hp[(r0 + r) * 32 + lane] = a[r];
    } else {
        for (int r = r0; r < N; r++) {
            const float4* xp = (const float4*)(x + (size_t)r * C_IN);
            float2 acc = make_float2(0.f, 0.f);
#pragma unroll
            for (int k4 = 0; k4 < C_IN / 4; k4++) {
                float4 xv = __ldg(&xp[k4]);
                float2 w0 = Ws[(k4 * 4 + 0) * 32 + lane];
                float2 w1 = Ws[(k4 * 4 + 1) * 32 + lane];
                float2 w2 = Ws[(k4 * 4 + 2) * 32 + lane];
                float2 w3 = Ws[(k4 * 4 + 3) * 32 + lane];
                acc.x += xv.x * w0.x + xv.y * w1.x + xv.z * w2.x + xv.w * w3.x;
                acc.y += xv.x * w0.y + xv.y * w1.y + xv.z * w2.y + xv.w * w3.y;
            }
            ((float2*)g_h1)[r * 32 + lane] = acc;
        }
    }
}

// ---------------- scan phase B: scan block totals (1 block) ----------------
__global__ void k_scanB(int nblk) {
    __shared__ int s[128];
    int tid = threadIdx.x;
    int own = (tid < nblk) ? g_bsum[tid] : 0;
    s[tid] = own;
    __syncthreads();
#pragma unroll
    for (int off = 1; off < 128; off <<= 1) {
        int v = (tid >= off) ? s[tid - off] : 0;
        __syncthreads();
        s[tid] += v;
        __syncthreads();
    }
    if (tid < nblk) g_bsum[tid] = s[tid] - own;
}

// ---------------- scan phase C: add offsets, init cursor, dinv -------------
__global__ void k_scanC(int N) {
    int i = blockIdx.x * blockDim.x + threadIdx.x;
    if (i < N) {
        int rs = g_rowstart[i] + g_bsum[i / SCAN_BLK];
        g_rowstart[i] = rs;
        g_cursor[i] = rs;
        int d = g_deg[i];
        g_dinv[i] = (d > 0) ? rsqrtf((float)d) : 0.f;
    }
}

// ---------------- bucket edges by dst (sorted (src, norm) list) ------------
__global__ void k_bucket(const void* __restrict__ ei, int E) {
    int e = blockIdx.x * blockDim.x + threadIdx.x;
    if (e < E) {
        int src, dst;
        load_edge(ei, e, E, src, dst);
        float norm = __ldg(&g_dinv[src]) * __ldg(&g_dinv[dst]);
        int pos = atomicAdd(&g_cursor[dst], 1);
        g_edge[pos] = make_int2(src, __float_as_int(norm));
    }
}

// ---------------- layer1 aggregate + bias + relu + GEMM2 (warp per node) ---
__global__ void k_agg1g2(const float* __restrict__ W2, const float* __restrict__ b1, int N) {
    __shared__ float Ws[HID * COUT + 64];   // padded: o1 path reads up to +63
    __shared__ float b1s[HID];
    int tid = threadIdx.x;
    for (int i = tid; i < HID * COUT + 64; i += blockDim.x)
        Ws[i] = (i < HID * COUT) ? W2[i] : 0.f;
    if (tid < HID) b1s[tid] = b1[tid];
    __syncthreads();

    int row  = (blockIdx.x * blockDim.x + tid) >> 5;
    int lane = tid & 31;
    if (row >= N) return;

    int idx = g_rowstart[row];
    int end = idx + g_deg[row];

    float2 acc = make_float2(0.f, 0.f);
    const float2* h1p = (const float2*)g_h1;

    // peel to 16B alignment for int4 pair loads
    if ((idx & 1) && idx < end) {
        int2 e = __ldg((const int2*)&g_edge[idx]);
        float n = __int_as_float(e.y);
        float2 v = h1p[e.x * 32 + lane];
        acc.x += v.x * n; acc.y += v.y * n;
        idx++;
    }
    int npair = (end - idx) >> 1;
    const int4* p4 = (const int4*)(g_edge + idx);

    int nf = npair & ~3;                      // groups of 4 int4 = 8 edges
    for (int j = 0; j < nf; j += 4) {
        int4 ea = __ldg(&p4[j]);
        int4 eb = __ldg(&p4[j + 1]);
        int4 ec = __ldg(&p4[j + 2]);
        int4 ed = __ldg(&p4[j + 3]);
        float2 v0 = h1p[ea.x * 32 + lane];
        float2 v1 = h1p[ea.z * 32 + lane];
        float2 v2 = h1p[eb.x * 32 + lane];
        float2 v3 = h1p[eb.z * 32 + lane];
        float2 v4 = h1p[ec.x * 32 + lane];
        float2 v5 = h1p[ec.z * 32 + lane];
        float2 v6 = h1p[ed.x * 32 + lane];
        float2 v7 = h1p[ed.z * 32 + lane];
        float n0 = __int_as_float(ea.y), n1 = __int_as_float(ea.w);
        float n2 = __int_as_float(eb.y), n3 = __int_as_float(eb.w);
        float n4 = __int_as_float(ec.y), n5 = __int_as_float(ec.w);
        float n6 = __int_as_float(ed.y), n7 = __int_as_float(ed.w);
        acc.x += v0.x * n0 + v1.x * n1 + v2.x * n2 + v3.x * n3
               + v4.x * n4 + v5.x * n5 + v6.x * n6 + v7.x * n7;
        acc.y += v0.y * n0 + v1.y * n1 + v2.y * n2 + v3.y * n3
               + v4.y * n4 + v5.y * n5 + v6.y * n6 + v7.y * n7;
    }
    for (int j = nf; j < npair; j++) {
        int4 ea = __ldg(&p4[j]);
        float2 v0 = h1p[ea.x * 32 + lane];
        float2 v1 = h1p[ea.z * 32 + lane];
        float n0 = __int_as_float(ea.y), n1 = __int_as_float(ea.w);
        acc.x += v0.x * n0 + v1.x * n1;
        acc.y += v0.y * n0 + v1.y * n1;
    }
    if ((end - idx) & 1) {
        int2 e = __ldg((const int2*)&g_edge[end - 1]);
        float n = __int_as_float(e.y);
        float2 v = h1p[e.x * 32 + lane];
        acc.x += v.x * n; acc.y += v.y * n;
    }

    // relu(agg + b1); lane holds cols 2*lane, 2*lane+1
    float c0 = fmaxf(acc.x + b1s[2 * lane],     0.f);
    float c1 = fmaxf(acc.y + b1s[2 * lane + 1], 0.f);

    float o0 = 0.f, o1 = 0.f;
#pragma unroll
    for (int k = 0; k < HID; k++) {
        float xv = __shfl_sync(0xffffffffu, (k & 1) ? c1 : c0, k >> 1);
        o0 += xv * Ws[k * COUT + lane];
        o1 += xv * Ws[k * COUT + lane + 32];
    }
    g_h2[row * COUT + lane] = o0;
    if (lane < COUT - 32) g_h2[row * COUT + 32 + lane] = o1;
}

// ---------------- layer2 aggregate + bias + log_softmax (warp per node) ----
__global__ void k_agg2fin(const float* __restrict__ b2, float* __restrict__ out, int N) {
    int tid = blockIdx.x * blockDim.x + threadIdx.x;
    int row = tid >> 5;
    int lane = tid & 31;
    if (row >= N) return;

    int idx = g_rowstart[row];
    int end = idx + g_deg[row];
    bool has1 = lane < (COUT - 32);
    int col1  = has1 ? (32 + lane) : lane;   // safe dummy for inactive lanes

    float a0 = 0.f, a1 = 0.f;

    if ((idx & 1) && idx < end) {
        int2 e = __ldg((const int2*)&g_edge[idx]);
        float n = __int_as_float(e.y);
        a0 += g_h2[e.x * COUT + lane] * n;
        a1 += g_h2[e.x * COUT + col1] * n;
        idx++;
    }
    int npair = (end - idx) >> 1;
    const int4* p4 = (const int4*)(g_edge + idx);

    int nf = npair & ~3;
    for (int j = 0; j < nf; j += 4) {
        int4 ea = __ldg(&p4[j]);
        int4 eb = __ldg(&p4[j + 1]);
        int4 ec = __ldg(&p4[j + 2]);
        int4 ed = __ldg(&p4[j + 3]);
        float n0 = __int_as_float(ea.y), n1 = __int_as_float(ea.w);
        float n2 = __int_as_float(eb.y), n3 = __int_as_float(eb.w);
        float n4 = __int_as_float(ec.y), n5 = __int_as_float(ec.w);
        float n6 = __int_as_float(ed.y), n7 = __int_as_float(ed.w);
        float p0 = g_h2[ea.x * COUT + lane], q0 = g_h2[ea.x * COUT + col1];
        float p1 = g_h2[ea.z * COUT + lane], q1 = g_h2[ea.z * COUT + col1];
        float p2 = g_h2[eb.x * COUT + lane], q2 = g_h2[eb.x * COUT + col1];
        float p3 = g_h2[eb.z * COUT + lane], q3 = g_h2[eb.z * COUT + col1];
        float p4v = g_h2[ec.x * COUT + lane], q4 = g_h2[ec.x * COUT + col1];
        float p5 = g_h2[ec.z * COUT + lane], q5 = g_h2[ec.z * COUT + col1];
        float p6 = g_h2[ed.x * COUT + lane], q6 = g_h2[ed.x * COUT + col1];
        float p7 = g_h2[ed.z * COUT + lane], q7 = g_h2[ed.z * COUT + col1];
        a0 += p0 * n0 + p1 * n1 + p2 * n2 + p3 * n3
            + p4v * n4 + p5 * n5 + p6 * n6 + p7 * n7;
        a1 += q0 * n0 + q1 * n1 + q2 * n2 + q3 * n3
            + q4 * n4 + q5 * n5 + q6 * n6 + q7 * n7;
    }
    for (int j = nf; j < npair; j++) {
        int4 ea = __ldg(&p4[j]);
        float n0 = __int_as_float(ea.y), n1 = __int_as_float(ea.w);
        a0 += g_h2[ea.x * COUT + lane] * n0 + g_h2[ea.z * COUT + lane] * n1;
        a1 += g_h2[ea.x * COUT + col1] * n0 + g_h2[ea.z * COUT + col1] * n1;
    }
    if ((end - idx) & 1) {
        int2 e = __ldg((const int2*)&g_edge[end - 1]);
        float n = __int_as_float(e.y);
        a0 += g_h2[e.x * COUT + lane] * n;
        a1 += g_h2[e.x * COUT + col1] * n;
    }

    float v0 = a0 + b2[lane];
    float v1 = has1 ? (a1 + b2[32 + lane]) : -CUDART_INF_F;

    float mx = fmaxf(v0, v1);
#pragma unroll
    for (int o = 16; o; o >>= 1) mx = fmaxf(mx, __shfl_xor_sync(0xffffffffu, mx, o));

    float sm = __expf(v0 - mx) + (has1 ? __expf(v1 - mx) : 0.f);
#pragma unroll
    for (int o = 16; o; o >>= 1) sm += __shfl_xor_sync(0xffffffffu, sm, o);

    float lg = mx + logf(sm);
    out[row * COUT + lane] = v0 - lg;
    if (has1) out[row * COUT + 32 + lane] = v1 - lg;
}

// ---------------- launch ----------------------------------------------------
extern "C" void kernel_launch(void* const* d_in, const int* in_sizes, int n_in,
                              void* d_out, int out_size) {
    const float* x  = (const float*)d_in[0];
    const void*  ei = d_in[1];
    const float* W1 = (const float*)d_in[2];
    const float* b1 = (const float*)d_in[3];
    const float* W2 = (const float*)d_in[4];
    const float* b2 = (const float*)d_in[5];
    float* out = (float*)d_out;

    int N = in_sizes[0] / C_IN;     // 100000
    int E = in_sizes[1] / 2;        // 3200000
    int nblk = (N + SCAN_BLK - 1) / SCAN_BLK;   // 98

    int g1warps = (N + 7) / 8;      // 8 rows per warp
    k_init   <<<256, 256>>>((const int*)ei, N);                 // idx 0
    k_hist   <<<(E + 255) / 256, 256>>>(ei, E);                 // idx 1
    k_scanA  <<<nblk, SCAN_BLK>>>(N);                           // idx 2
    k_gemm1  <<<(g1warps * 32 + 255) / 256, 256>>>(x, W1, N);   // idx 3 (profiled)
    k_scanB  <<<1, 128>>>(nblk);                                // idx 4
    k_scanC  <<<(N + 255) / 256, 256>>>(N);                     // idx 5
    k_bucket <<<(E + 255) / 256, 256>>>(ei, E);                 // idx 6
    k_agg1g2 <<<(N * 32 + 255) / 256, 256>>>(W2, b1, N);        // idx 7
    k_agg2fin<<<(N * 32 + 255) / 256, 256>>>(b2, out, N);       // idx 8
}

// round 15
// speedup vs baseline: 1.6365x; 1.0498x over previous
#include <cuda_runtime.h>
#include <cuda_bf16.h>
#include <math_constants.h>

// R15: fork/join graph capture — gemm1 (SM-bound, 82us) runs concurrently with
// the hist->scan->bucket chain (L2/atomic-bound, ~100us). Kernels = R14.

#define N_NODES 100000
#define N_EDGES 3200000
#define C_IN    128
#define HID     64
#define COUT    40
#define SCAN_BLK 1024

// ---------------- scratch (device globals; no allocation allowed) ----------
__device__ __align__(16) float g_dinv[N_NODES];
__device__ __align__(16) int   g_deg [N_NODES];
__device__ __align__(16) int   g_rowstart[N_NODES];
__device__ __align__(16) int   g_cursor  [N_NODES];
__device__ __align__(16) int   g_bsum[128];
__device__ __align__(16) int2  g_edge[N_EDGES];          // {src, norm bits} dst-sorted
__device__ __align__(16) float g_h1  [N_NODES * HID];    // x @ W1
__device__ __align__(16) float g_h2  [N_NODES * COUT];   // layer-1 output
__device__ int g_idx64;

// ---------------- edge-index accessor (dtype-agnostic) ---------------------
__device__ __forceinline__ void load_edge(const void* ei, int e, int E,
                                          int& src, int& dst) {
    if (g_idx64) {
        const long long* p = (const long long*)ei;
        src = (int)__ldg(&p[e]);
        dst = (int)__ldg(&p[E + e]);
    } else {
        const int* p = (const int*)ei;
        src = __ldg(&p[e]);
        dst = __ldg(&p[E + e]);
    }
}

// ---------------- init: dtype detect (thread 0) + zero degree --------------
__global__ void k_init(const int* __restrict__ ei32, int N) {
    int i = blockIdx.x * blockDim.x + threadIdx.x;
    if (i == 0) {
        int all_zero = 1;
        for (int j = 0; j < 64; j++)
            if (ei32[2 * j + 1] != 0) { all_zero = 0; break; }
        g_idx64 = all_zero;
    }
    int stride = gridDim.x * blockDim.x;
    for (int j = i; j < N; j += stride) g_deg[j] = 0;
}

// ---------------- histogram of dst (= in-degree) ---------------------------
__global__ void k_hist(const void* __restrict__ ei, int E) {
    int e = blockIdx.x * blockDim.x + threadIdx.x;
    if (e < E) {
        int dst;
        if (g_idx64) dst = (int)__ldg(&((const long long*)ei)[E + e]);
        else         dst = __ldg(&((const int*)ei)[E + e]);
        atomicAdd(&g_deg[dst], 1);
    }
}

// ---------------- scan phase A: per-block exclusive scan -------------------
__global__ void k_scanA(int N) {
    __shared__ int s[SCAN_BLK];
    int tid = threadIdx.x;
    int i = blockIdx.x * SCAN_BLK + tid;
    int own = (i < N) ? g_deg[i] : 0;
    s[tid] = own;
    __syncthreads();
#pragma unroll
    for (int off = 1; off < SCAN_BLK; off <<= 1) {
        int v = (tid >= off) ? s[tid - off] : 0;
        __syncthreads();
        s[tid] += v;
        __syncthreads();
    }
    if (i < N) g_rowstart[i] = s[tid] - own;
    if (tid == SCAN_BLK - 1) g_bsum[blockIdx.x] = s[tid];
}

// ---------------- GEMM1: h1 = x @ W1 (8 rows per warp, smem W reuse) -------
__global__ void k_gemm1(const float* __restrict__ x, const float* __restrict__ W1, int N) {
    __shared__ float2 Ws[C_IN * 32];   // [k][colpair]
    int tid = threadIdx.x;
    const float2* W2p = (const float2*)W1;
    for (int i = tid; i < C_IN * 32; i += blockDim.x) Ws[i] = W2p[i];
    __syncthreads();

    int warp = (blockIdx.x * blockDim.x + tid) >> 5;
    int lane = tid & 31;
    int r0 = warp * 8;
    if (r0 >= N) return;

    if (r0 + 7 < N) {
        float2 a[8];
#pragma unroll
        for (int r = 0; r < 8; r++) a[r] = make_float2(0.f, 0.f);
#pragma unroll 8
        for (int k4 = 0; k4 < C_IN / 4; k4++) {
            float2 w0 = Ws[(k4 * 4 + 0) * 32 + lane];
            float2 w1 = Ws[(k4 * 4 + 1) * 32 + lane];
            float2 w2 = Ws[(k4 * 4 + 2) * 32 + lane];
            float2 w3 = Ws[(k4 * 4 + 3) * 32 + lane];
#pragma unroll
            for (int r = 0; r < 8; r++) {
                float4 xv = __ldg((const float4*)(x + (size_t)(r0 + r) * C_IN) + k4);
                a[r].x += xv.x * w0.x + xv.y * w1.x + xv.z * w2.x + xv.w * w3.x;
                a[r].y += xv.x * w0.y + xv.y * w1.y + xv.z * w2.y + xv.w * w3.y;
            }
        }
        float2* hp = (float2*)g_h1;
#pragma unroll
        for (int r = 0; r < 8; r++) hp[(r0 + r) * 32 + lane] = a[r];
    } else {
        for (int r = r0; r < N; r++) {
            const float4* xp = (const float4*)(x + (size_t)r * C_IN);
            float2 acc = make_float2(0.f, 0.f);
#pragma unroll
            for (int k4 = 0; k4 < C_IN / 4; k4++) {
                float4 xv = __ldg(&xp[k4]);
                float2 w0 = Ws[(k4 * 4 + 0) * 32 + lane];
                float2 w1 = Ws[(k4 * 4 + 1) * 32 + lane];
                float2 w2 = Ws[(k4 * 4 + 2) * 32 + lane];
                float2 w3 = Ws[(k4 * 4 + 3) * 32 + lane];
                acc.x += xv.x * w0.x + xv.y * w1.x + xv.z * w2.x + xv.w * w3.x;
                acc.y += xv.x * w0.y + xv.y * w1.y + xv.z * w2.y + xv.w * w3.y;
            }
            ((float2*)g_h1)[r * 32 + lane] = acc;
        }
    }
}

// ---------------- scan phase B: scan block totals (1 block) ----------------
__global__ void k_scanB(int nblk) {
    __shared__ int s[128];
    int tid = threadIdx.x;
    int own = (tid < nblk) ? g_bsum[tid] : 0;
    s[tid] = own;
    __syncthreads();
#pragma unroll
    for (int off = 1; off < 128; off <<= 1) {
        int v = (tid >= off) ? s[tid - off] : 0;
        __syncthreads();
        s[tid] += v;
        __syncthreads();
    }
    if (tid < nblk) g_bsum[tid] = s[tid] - own;
}

// ---------------- scan phase C: add offsets, init cursor, dinv -------------
__global__ void k_scanC(int N) {
    int i = blockIdx.x * blockDim.x + threadIdx.x;
    if (i < N) {
        int rs = g_rowstart[i] + g_bsum[i / SCAN_BLK];
        g_rowstart[i] = rs;
        g_cursor[i] = rs;
        int d = g_deg[i];
        g_dinv[i] = (d > 0) ? rsqrtf((float)d) : 0.f;
    }
}

// ---------------- bucket edges by dst (sorted (src, norm) list) ------------
__global__ void k_bucket(const void* __restrict__ ei, int E) {
    int e = blockIdx.x * blockDim.x + threadIdx.x;
    if (e < E) {
        int src, dst;
        load_edge(ei, e, E, src, dst);
        float norm = __ldg(&g_dinv[src]) * __ldg(&g_dinv[dst]);
        int pos = atomicAdd(&g_cursor[dst], 1);
        g_edge[pos] = make_int2(src, __float_as_int(norm));
    }
}

// ---------------- layer1 aggregate + bias + relu + GEMM2 (warp per node) ---
__global__ void k_agg1g2(const float* __restrict__ W2, const float* __restrict__ b1, int N) {
    __shared__ float Ws[HID * COUT + 64];   // padded: o1 path reads up to +63
    __shared__ float b1s[HID];
    int tid = threadIdx.x;
    for (int i = tid; i < HID * COUT + 64; i += blockDim.x)
        Ws[i] = (i < HID * COUT) ? W2[i] : 0.f;
    if (tid < HID) b1s[tid] = b1[tid];
    __syncthreads();

    int row  = (blockIdx.x * blockDim.x + tid) >> 5;
    int lane = tid & 31;
    if (row >= N) return;

    int idx = g_rowstart[row];
    int end = idx + g_deg[row];

    float2 acc = make_float2(0.f, 0.f);
    const float2* h1p = (const float2*)g_h1;

    // peel to 16B alignment for int4 pair loads
    if ((idx & 1) && idx < end) {
        int2 e = __ldg((const int2*)&g_edge[idx]);
        float n = __int_as_float(e.y);
        float2 v = h1p[e.x * 32 + lane];
        acc.x += v.x * n; acc.y += v.y * n;
        idx++;
    }
    int npair = (end - idx) >> 1;
    const int4* p4 = (const int4*)(g_edge + idx);

    int nf = npair & ~3;                      // groups of 4 int4 = 8 edges
    for (int j = 0; j < nf; j += 4) {
        int4 ea = __ldg(&p4[j]);
        int4 eb = __ldg(&p4[j + 1]);
        int4 ec = __ldg(&p4[j + 2]);
        int4 ed = __ldg(&p4[j + 3]);
        float2 v0 = h1p[ea.x * 32 + lane];
        float2 v1 = h1p[ea.z * 32 + lane];
        float2 v2 = h1p[eb.x * 32 + lane];
        float2 v3 = h1p[eb.z * 32 + lane];
        float2 v4 = h1p[ec.x * 32 + lane];
        float2 v5 = h1p[ec.z * 32 + lane];
        float2 v6 = h1p[ed.x * 32 + lane];
        float2 v7 = h1p[ed.z * 32 + lane];
        float n0 = __int_as_float(ea.y), n1 = __int_as_float(ea.w);
        float n2 = __int_as_float(eb.y), n3 = __int_as_float(eb.w);
        float n4 = __int_as_float(ec.y), n5 = __int_as_float(ec.w);
        float n6 = __int_as_float(ed.y), n7 = __int_as_float(ed.w);
        acc.x += v0.x * n0 + v1.x * n1 + v2.x * n2 + v3.x * n3
               + v4.x * n4 + v5.x * n5 + v6.x * n6 + v7.x * n7;
        acc.y += v0.y * n0 + v1.y * n1 + v2.y * n2 + v3.y * n3
               + v4.y * n4 + v5.y * n5 + v6.y * n6 + v7.y * n7;
    }
    for (int j = nf; j < npair; j++) {
        int4 ea = __ldg(&p4[j]);
        float2 v0 = h1p[ea.x * 32 + lane];
        float2 v1 = h1p[ea.z * 32 + lane];
        float n0 = __int_as_float(ea.y), n1 = __int_as_float(ea.w);
        acc.x += v0.x * n0 + v1.x * n1;
        acc.y += v0.y * n0 + v1.y * n1;
    }
    if ((end - idx) & 1) {
        int2 e = __ldg((const int2*)&g_edge[end - 1]);
        float n = __int_as_float(e.y);
        float2 v = h1p[e.x * 32 + lane];
        acc.x += v.x * n; acc.y += v.y * n;
    }

    // relu(agg + b1); lane holds cols 2*lane, 2*lane+1
    float c0 = fmaxf(acc.x + b1s[2 * lane],     0.f);
    float c1 = fmaxf(acc.y + b1s[2 * lane + 1], 0.f);

    float o0 = 0.f, o1 = 0.f;
#pragma unroll
    for (int k = 0; k < HID; k++) {
        float xv = __shfl_sync(0xffffffffu, (k & 1) ? c1 : c0, k >> 1);
        o0 += xv * Ws[k * COUT + lane];
        o1 += xv * Ws[k * COUT + lane + 32];
    }
    g_h2[row * COUT + lane] = o0;
    if (lane < COUT - 32) g_h2[row * COUT + 32 + lane] = o1;
}

// ---------------- layer2 aggregate + bias + log_softmax (warp per node) ----
__global__ void k_agg2fin(const float* __restrict__ b2, float* __restrict__ out, int N) {
    int tid = blockIdx.x * blockDim.x + threadIdx.x;
    int row = tid >> 5;
    int lane = tid & 31;
    if (row >= N) return;

    int idx = g_rowstart[row];
    int end = idx + g_deg[row];
    bool has1 = lane < (COUT - 32);
    int col1  = has1 ? (32 + lane) : lane;   // safe dummy for inactive lanes

    float a0 = 0.f, a1 = 0.f;

    if ((idx & 1) && idx < end) {
        int2 e = __ldg((const int2*)&g_edge[idx]);
        float n = __int_as_float(e.y);
        a0 += g_h2[e.x * COUT + lane] * n;
        a1 += g_h2[e.x * COUT + col1] * n;
        idx++;
    }
    int npair = (end - idx) >> 1;
    const int4* p4 = (const int4*)(g_edge + idx);

    int nf = npair & ~3;
    for (int j = 0; j < nf; j += 4) {
        int4 ea = __ldg(&p4[j]);
        int4 eb = __ldg(&p4[j + 1]);
        int4 ec = __ldg(&p4[j + 2]);
        int4 ed = __ldg(&p4[j + 3]);
        float n0 = __int_as_float(ea.y), n1 = __int_as_float(ea.w);
        float n2 = __int_as_float(eb.y), n3 = __int_as_float(eb.w);
        float n4 = __int_as_float(ec.y), n5 = __int_as_float(ec.w);
        float n6 = __int_as_float(ed.y), n7 = __int_as_float(ed.w);
        float p0 = g_h2[ea.x * COUT + lane], q0 = g_h2[ea.x * COUT + col1];
        float p1 = g_h2[ea.z * COUT + lane], q1 = g_h2[ea.z * COUT + col1];
        float p2 = g_h2[eb.x * COUT + lane], q2 = g_h2[eb.x * COUT + col1];
        float p3 = g_h2[eb.z * COUT + lane], q3 = g_h2[eb.z * COUT + col1];
        float p4v = g_h2[ec.x * COUT + lane], q4 = g_h2[ec.x * COUT + col1];
        float p5 = g_h2[ec.z * COUT + lane], q5 = g_h2[ec.z * COUT + col1];
        float p6 = g_h2[ed.x * COUT + lane], q6 = g_h2[ed.x * COUT + col1];
        float p7 = g_h2[ed.z * COUT + lane], q7 = g_h2[ed.z * COUT + col1];
        a0 += p0 * n0 + p1 * n1 + p2 * n2 + p3 * n3
            + p4v * n4 + p5 * n5 + p6 * n6 + p7 * n7;
        a1 += q0 * n0 + q1 * n1 + q2 * n2 + q3 * n3
            + q4 * n4 + q5 * n5 + q6 * n6 + q7 * n7;
    }
    for (int j = nf; j < npair; j++) {
        int4 ea = __ldg(&p4[j]);
        float n0 = __int_as_float(ea.y), n1 = __int_as_float(ea.w);
        a0 += g_h2[ea.x * COUT + lane] * n0 + g_h2[ea.z * COUT + lane] * n1;
        a1 += g_h2[ea.x * COUT + col1] * n0 + g_h2[ea.z * COUT + col1] * n1;
    }
    if ((end - idx) & 1) {
        int2 e = __ldg((const int2*)&g_edge[end - 1]);
        float n = __int_as_float(e.y);
        a0 += g_h2[e.x * COUT + lane] * n;
        a1 += g_h2[e.x * COUT + col1] * n;
    }

    float v0 = a0 + b2[lane];
    float v1 = has1 ? (a1 + b2[32 + lane]) : -CUDART_INF_F;

    float mx = fmaxf(v0, v1);
#pragma unroll
    for (int o = 16; o; o >>= 1) mx = fmaxf(mx, __shfl_xor_sync(0xffffffffu, mx, o));

    float sm = __expf(v0 - mx) + (has1 ? __expf(v1 - mx) : 0.f);
#pragma unroll
    for (int o = 16; o; o >>= 1) sm += __shfl_xor_sync(0xffffffffu, sm, o);

    float lg = mx + logf(sm);
    out[row * COUT + lane] = v0 - lg;
    if (has1) out[row * COUT + 32 + lane] = v1 - lg;
}

// ---------------- launch: fork gemm1 parallel to hist->scan->bucket --------
extern "C" void kernel_launch(void* const* d_in, const int* in_sizes, int n_in,
                              void* d_out, int out_size) {
    const float* x  = (const float*)d_in[0];
    const void*  ei = d_in[1];
    const float* W1 = (const float*)d_in[2];
    const float* b1 = (const float*)d_in[3];
    const float* W2 = (const float*)d_in[4];
    const float* b2 = (const float*)d_in[5];
    float* out = (float*)d_out;

    int N = in_sizes[0] / C_IN;     // 100000
    int E = in_sizes[1] / 2;        // 3200000
    int nblk = (N + SCAN_BLK - 1) / SCAN_BLK;   // 98
    int g1warps = (N + 7) / 8;      // 8 rows per warp

    cudaStream_t s2;
    cudaStreamCreateWithFlags(&s2, cudaStreamNonBlocking);
    cudaEvent_t ev_fork, ev_join;
    cudaEventCreateWithFlags(&ev_fork, cudaEventDisableTiming);
    cudaEventCreateWithFlags(&ev_join, cudaEventDisableTiming);

    // fork point (before any work; gemm1 has no deps on the CSR chain)
    cudaEventRecord(ev_fork, 0);
    cudaStreamWaitEvent(s2, ev_fork, 0);
    k_gemm1<<<(g1warps * 32 + 255) / 256, 256, 0, s2>>>(x, W1, N);
    cudaEventRecord(ev_join, s2);

    // CSR build chain on the default stream
    k_init   <<<256, 256>>>((const int*)ei, N);
    k_hist   <<<(E + 255) / 256, 256>>>(ei, E);
    k_scanA  <<<nblk, SCAN_BLK>>>(N);
    k_scanB  <<<1, 128>>>(nblk);
    k_scanC  <<<(N + 255) / 256, 256>>>(N);
    k_bucket <<<(E + 255) / 256, 256>>>(ei, E);

    // join: aggs need both h1 (gemm1) and the CSR
    cudaStreamWaitEvent(0, ev_join, 0);
    k_agg1g2 <<<(N * 32 + 255) / 256, 256>>>(W2, b1, N);
    k_agg2fin<<<(N * 32 + 255) / 256, 256>>>(b2, out, N);

    cudaEventDestroy(ev_fork);
    cudaEventDestroy(ev_join);
    cudaStreamDestroy(s2);
}